// round 6
// baseline (speedup 1.0000x reference)
#include <cuda_runtime.h>

// EHD layer, fully fused, v5:
//   3x3 conv (8 filters) -> argmax+thresh -> byte-packed one-hot ->
//   separable 5x5 box sum -> magic-number unpack -> out[B,9,1018,1018].
//
// v5 vs v4:
//  - I2F-free unpack: PRMT builds 0x4B0000XX (=2^23+cnt as f32 bits), one
//    FFMA(f, 1/25, -2^23/25) yields cnt*(1/25) exactly (2^23*fl(1/25) is
//    exactly representable -> single rounding, bit-identical to v4).
//  - stage 3: sliding-window 5-tap (10 u64 adds / 4 outputs vs 16) with
//    LDS.128/STS.128 (4 loads vs 20).
//  - stage 4: s_h restrided to 36 -> even columns 16B-aligned -> one
//    LDS.128 per row serves BOTH columns of the pair (5 loads vs 10).

#define NOR    8
#define NBINS  9
#define OUT_H  1018
#define OUT_W  1018
#define THRESH 0.9f

#define T   28            // output tile
#define IT  32            // index tile  (T+4)
#define LT  34            // input tile  (T+6)

#define NTHREADS 256

typedef unsigned long long u64;

__constant__ float c_masks[NOR * 9];

__device__ __forceinline__ float cnt_scale(unsigned word, int byte_sel) {
    // word's byte[byte_sel] = count in 0..25  ->  count * fl(1/25)
    const unsigned bits = __byte_perm(word, 0x4B000000u, 0x7440 | byte_sel);
    const float f = __int_as_float(bits);                     // 2^23 + cnt
    return fmaf(f, (1.0f / 25.0f), -(8388608.0f * (1.0f / 25.0f)));
}

__global__ __launch_bounds__(NTHREADS, 6)
void ehd_fused_kernel(const float* __restrict__ x,
                      float* __restrict__ out)
{
    __shared__ float s_in[LT][36];        // 34x36 f32
    __shared__ u64 s_oh[IT][36];          // byte-packed one-hot (cols 32..35 = 0)
    __shared__ u64 s_h [IT][36];          // horizontal 5-sums (stride 36 for 16B align)

    const int tid  = threadIdx.x;
    const int lane = tid & 31;
    const int wid  = tid >> 5;
    const int ox   = blockIdx.x * T;
    const int oy   = blockIdx.y * T;
    const int b    = blockIdx.z;

    if (tid < IT * 4) s_oh[tid >> 2][32 + (tid & 3)] = 0ULL;  // zero halo pad cols

    // ---- stage 1: load 34x34 input tile (zero-pad OOB; pad only feeds index
    // pixels no valid output window references) ----
    const float* xb = x + (size_t)b * (1024 * 1024);
    for (int r = wid; r < LT; r += 8) {
        const int gy = oy + r;
        for (int c = lane; c < LT; c += 32) {
            const int gx = ox + c;
            float v = 0.0f;
            if (gy < 1024 && gx < 1024) v = xb[gy * 1024 + gx];
            s_in[r][c] = v;
        }
    }
    __syncthreads();

    // ---- stage 2: conv + argmax + threshold + byte-packed one-hot ----
    // thread -> column c = lane, rows rbase..rbase+3 (shared 6x3 window strip)
    {
        const int c     = lane;
        const int rbase = wid << 2;

        float w[6][3];
#pragma unroll
        for (int j = 0; j < 6; j++)
#pragma unroll
            for (int k = 0; k < 3; k++)
                w[j][k] = s_in[rbase + j][c + k];

        float best[4];
        int   bi[4];
#pragma unroll
        for (int p = 0; p < 4; p++) { best[p] = -3.4e38f; bi[p] = 0; }

#pragma unroll
        for (int f = 0; f < NOR; f++) {
            const float m0 = c_masks[f * 9 + 0], m1 = c_masks[f * 9 + 1], m2 = c_masks[f * 9 + 2];
            const float m3 = c_masks[f * 9 + 3], m4 = c_masks[f * 9 + 4], m5 = c_masks[f * 9 + 5];
            const float m6 = c_masks[f * 9 + 6], m7 = c_masks[f * 9 + 7], m8 = c_masks[f * 9 + 8];
#pragma unroll
            for (int p = 0; p < 4; p++) {
                float acc = w[p][0] * m0;
                acc = fmaf(w[p    ][1], m1, acc);
                acc = fmaf(w[p    ][2], m2, acc);
                acc = fmaf(w[p + 1][0], m3, acc);
                acc = fmaf(w[p + 1][1], m4, acc);
                acc = fmaf(w[p + 1][2], m5, acc);
                acc = fmaf(w[p + 2][0], m6, acc);
                acc = fmaf(w[p + 2][1], m7, acc);
                acc = fmaf(w[p + 2][2], m8, acc);
                // strict > keeps FIRST max (jnp.argmax tie-break)
                if (acc > best[p]) { best[p] = acc; bi[p] = f; }
            }
        }
#pragma unroll
        for (int p = 0; p < 4; p++) {
            const int idx = (best[p] < THRESH) ? NOR : bi[p];
            // bins 0..7 -> one byte of a u64; bin 8 (no-edge) -> 0 (implicit)
            s_oh[rbase + p][c] = (idx < NOR) ? (1ULL << (idx << 3)) : 0ULL;
        }
    }
    __syncthreads();

    // ---- stage 3: horizontal 5-tap sliding sum, 128-bit smem traffic ----
    // thread -> row r = tid>>3, cols c0..c0+3 where c0 = (tid&7)*4.
    // Loads oh[c0..c0+7] (cols 32..35 are the zero pad). Byte-wise no borrow:
    // each byte of (a+..+e) >= corresponding byte of a.
    {
        const int r  = tid >> 3;
        const int c0 = (tid & 7) << 2;
        const ulonglong2* src = (const ulonglong2*)&s_oh[r][c0];
        const ulonglong2 p0 = src[0], p1 = src[1], p2 = src[2], p3 = src[3];
        const u64 a = p0.x, bb = p0.y, cc = p1.x, d = p1.y,
                  e = p2.x, f  = p2.y, g  = p3.x, h = p3.y;
        const u64 s0 = a + bb + cc + d + e;
        const u64 s1 = s0 - a  + f;
        const u64 s2 = s1 - bb + g;
        const u64 s3 = s2 - cc + h;
        ulonglong2* dst = (ulonglong2*)&s_h[r][c0];
        dst[0] = make_ulonglong2(s0, s1);
        dst[1] = make_ulonglong2(s2, s3);
    }
    __syncthreads();

    // ---- stage 4: vertical 5-tap on column pairs (one LDS.128 per row reads
    // both columns), magic-number unpack, float2 stores ----
    const size_t plane = (size_t)OUT_H * OUT_W;
    float* ob = out + (size_t)b * NBINS * plane;
#pragma unroll
    for (int it = 0; it < 2; it++) {
        const int u = tid + it * NTHREADS;
        if (u < 14 * T) {
            const int r  = u / 14;
            const int c  = (u - r * 14) * 2;
            const int gy = oy + r, gx = ox + c;
            if (gy < OUT_H && gx + 1 < OUT_W) {
                ulonglong2 q0 = *(const ulonglong2*)&s_h[r    ][c];
                ulonglong2 q1 = *(const ulonglong2*)&s_h[r + 1][c];
                ulonglong2 q2 = *(const ulonglong2*)&s_h[r + 2][c];
                ulonglong2 q3 = *(const ulonglong2*)&s_h[r + 3][c];
                ulonglong2 q4 = *(const ulonglong2*)&s_h[r + 4][c];
                const u64 v0 = q0.x + q1.x + q2.x + q3.x + q4.x;
                const u64 v1 = q0.y + q1.y + q2.y + q3.y + q4.y;
                const unsigned lo0 = (unsigned)v0, hi0 = (unsigned)(v0 >> 32);
                const unsigned lo1 = (unsigned)v1, hi1 = (unsigned)(v1 >> 32);

                float* p = ob + (size_t)gy * OUT_W + gx;
#pragma unroll
                for (int bin = 0; bin < 8; bin++) {
                    float2 v;
                    v.x = cnt_scale((bin < 4) ? lo0 : hi0, bin & 3);
                    v.y = cnt_scale((bin < 4) ? lo1 : hi1, bin & 3);
                    *(float2*)(p + (size_t)bin * plane) = v;
                }
                // bin 8 = 25 - sum of the other 8 counts; reuse exact path
                const unsigned s0 = __dp4a(lo0, 0x01010101u, __dp4a(hi0, 0x01010101u, 0u));
                const unsigned s1 = __dp4a(lo1, 0x01010101u, __dp4a(hi1, 0x01010101u, 0u));
                float2 v8;
                v8.x = cnt_scale(25u - s0, 0);
                v8.y = cnt_scale(25u - s1, 0);
                *(float2*)(p + (size_t)8 * plane) = v8;
            }
        }
    }
}

extern "C" void kernel_launch(void* const* d_in, const int* in_sizes, int n_in,
                              void* d_out, int out_size)
{
    const float* x     = (const float*)d_in[0];   // [B,1,1024,1024]
    const float* masks = (const float*)d_in[1];   // [8,1,3,3]
    float* out = (float*)d_out;                   // [B,9,1018,1018]

    const int batch = in_sizes[0] / (1024 * 1024);

    // masks -> constant bank (device-to-device async copy: graph-capturable)
    cudaMemcpyToSymbolAsync(c_masks, masks, NOR * 9 * sizeof(float), 0,
                            cudaMemcpyDeviceToDevice);

    dim3 grid((OUT_W + T - 1) / T, (OUT_H + T - 1) / T, batch);
    ehd_fused_kernel<<<grid, NTHREADS>>>(x, out);
}